// round 15
// baseline (speedup 1.0000x reference)
#include <cuda_runtime.h>
#include <cstdint>

// Problem constants
#define BB 128
#define DD 128
#define TT 2048
#define CC 64
#define TILE_T 512
#define DCH 32
#define NCH 4
#define THREADS 512
#define NWARP 16
#define NPROD 4
#define NCONS 12
#define PITCH32 17
#define NTILE 512
#define GRID 304                  // persistent: 152 SMs x 2 CTAs
#define NREP 8
#define ZROW (TILE_T * PITCH32)   // zero-row word index within a buffer (8704)
#define BUFW (ZROW + 16)          // words per buffer (8720)
#define PRE_N 704

// Scratch (allocation-free; self-reset each run so graph replays are identical)
__device__ float        g_S[NREP][CC * DD];
__device__ float        g_loss;
__device__ int          g_count[CC];
__device__ unsigned int g_done;
__device__ unsigned int g_ticket;

// smem layout (bytes)
#define SM_BUF0   0
#define SM_BUF1   34880
#define SM_SLOC   69760            // S_local: 64*128 f32 = 32768
#define SM_PRE    102528           // 704*4 = 2816
#define SM_HIST   105344
#define SM_START  105600
#define SM_CUR    105856
#define SM_CNT    106112
#define SM_WRED   106368
#define SM_WTOT   106432
#define SM_SLOT   106440
#define SM_TICK   106448
#define SM_TOTAL  106464

__global__ __launch_bounds__(THREADS, 2)
void cl_fused_kernel(const float* __restrict__ feature,
                     const int* __restrict__ label,
                     const float* __restrict__ centers,
                     float* __restrict__ out) {
    extern __shared__ char sm[];
    uint32_t*     buf0   = (uint32_t*)(sm + SM_BUF0);
    uint32_t*     buf1   = (uint32_t*)(sm + SM_BUF1);
    float*        sloc   = (float*)(sm + SM_SLOC);
    uint32_t*     pre    = (uint32_t*)(sm + SM_PRE);
    int*          hist   = (int*)(sm + SM_HIST);
    int*          starts = (int*)(sm + SM_START);
    int*          cursor = (int*)(sm + SM_CUR);
    int*          cntl   = (int*)(sm + SM_CNT);
    float*        wred   = (float*)(sm + SM_WRED);
    int*          wtot   = (int*)(sm + SM_WTOT);
    unsigned int* slot   = (unsigned int*)(sm + SM_SLOT);
    unsigned int* tick   = (unsigned int*)(sm + SM_TICK);

    const int tid  = threadIdx.x;
    const int lane = tid & 31;
    const int wid  = tid >> 5;
    const int rep  = blockIdx.x & (NREP - 1);
    const int lanelow = lane & 15;
    const int half    = lane >> 4;

    // Block-lifetime init: S_local, counts, zero-rows, first ticket
    for (int i = tid; i < CC * DD; i += THREADS) sloc[i] = 0.0f;
    if (tid < CC) cntl[tid] = 0;
    if (tid < 16) { buf0[ZROW + tid] = 0u; buf1[ZROW + tid] = 0u; }
    if (tid == 0) slot[0] = atomicAdd(&g_ticket, 1u);
    __syncthreads();

    unsigned cur = slot[0];
    float sumsq = 0.0f;
    const float4* f40 = (const float4*)feature;

    while (cur < NTILE) {
        const int b  = (int)(cur >> 2);
        const int t0 = ((int)cur & 3) * TILE_T;

        // ---- Prologue: labels, histogram, 4-padded scan, scatter ----
        if (tid < CC) hist[tid] = 0;
        __syncthreads();
        const int myl = label[b * TT + t0 + tid] & (CC - 1);   // tid == row
        atomicAdd(&hist[myl], 1);
        __syncthreads();

        {   // exclusive scan of 4-padded class sizes (warps 0/1 + carry)
            int m  = (tid < CC) ? hist[tid] : 0;
            int p4 = (m + 3) & ~3;
            int incl = p4;
            #pragma unroll
            for (int o = 1; o < 32; o <<= 1) {
                int n = __shfl_up_sync(0xffffffffu, incl, o);
                if (lane >= o) incl += n;
            }
            if (wid < 2 && lane == 31) wtot[wid] = incl;
            __syncthreads();
            if (tid < CC) {
                int st = incl - p4 + (wid == 1 ? wtot[0] : 0);
                starts[tid] = st;
                cursor[tid] = st;
            }
            __syncthreads();
        }

        {   // scatter: desc = (t*17)<<4 | bankkey(t); pads -> zero-row
            int pos = atomicAdd(&cursor[myl], 1);
            pre[pos] = ((unsigned)(tid * PITCH32) << 4) | (unsigned)((tid >> 5) & 3);
            if (tid < CC) {
                int m  = hist[tid];
                int st = starts[tid];
                int p4 = (m + 3) & ~3;
                for (int k = m; k < p4; k++) pre[st + k] = (unsigned)ZROW << 4;
                cntl[tid] += m;                       // smem count accumulation
            }
        }
        __syncthreads();   // pre[] ready

        // ---- Pipeline: 4 producer warps fill buf[it&1]; 12 consumers drain ----
        for (int it = 0; it <= NCH; it++) {
            if (wid < NPROD) {
                if (it < NCH) {
                    uint32_t* buf = (it & 1) ? buf1 : buf0;
                    const int t4 = tid;                        // 0..127
                    const int kk = (t4 >> 3) & 3;
                    const float4* f4 = f40
                        + ((long long)b * DD + it * DCH) * (TT / 4) + (t0 >> 2) + t4;
                    #pragma unroll
                    for (int h = 0; h < 4; h++) {
                        float4 A[4], B[4];
                        #pragma unroll
                        for (int j = 0; j < 4; j++) {          // 8 LDG.128 in flight
                            int p = h * 4 + j;
                            A[j] = f4[(2 * p)     * (TT / 4)];
                            B[j] = f4[(2 * p + 1) * (TT / 4)];
                        }
                        #pragma unroll
                        for (int j = 0; j < 4; j++) {
                            int p    = h * 4 + j;
                            int base = t4 * (4 * PITCH32) + (p ^ kk);
                            uint32_t u0, u1, u2, u3;           // hi = odd d, lo = even
                            asm("cvt.rn.bf16x2.f32 %0, %1, %2;" : "=r"(u0) : "f"(B[j].x), "f"(A[j].x));
                            asm("cvt.rn.bf16x2.f32 %0, %1, %2;" : "=r"(u1) : "f"(B[j].y), "f"(A[j].y));
                            asm("cvt.rn.bf16x2.f32 %0, %1, %2;" : "=r"(u2) : "f"(B[j].z), "f"(A[j].z));
                            asm("cvt.rn.bf16x2.f32 %0, %1, %2;" : "=r"(u3) : "f"(B[j].w), "f"(A[j].w));
                            buf[base]               = u0;
                            buf[base + PITCH32]     = u1;
                            buf[base + 2 * PITCH32] = u2;
                            buf[base + 3 * PITCH32] = u3;
                            sumsq = fmaf(A[j].x, A[j].x, sumsq); sumsq = fmaf(A[j].y, A[j].y, sumsq);
                            sumsq = fmaf(A[j].z, A[j].z, sumsq); sumsq = fmaf(A[j].w, A[j].w, sumsq);
                            sumsq = fmaf(B[j].x, B[j].x, sumsq); sumsq = fmaf(B[j].y, B[j].y, sumsq);
                            sumsq = fmaf(B[j].z, B[j].z, sumsq); sumsq = fmaf(B[j].w, B[j].w, sumsq);
                        }
                    }
                }
                if (it == 2 && tid == 0) slot[1] = atomicAdd(&g_ticket, 1u);
            } else {
                // CONSUMER: gather chunk it-1; accumulate into S_local (no atomics)
                if (it >= 1) {
                    const int ch = it - 1;
                    const uint32_t* buf = (ch & 1) ? buf1 : buf0;
                    for (int c = wid - NPROD; c < CC; c += NCONS) {
                        const int m = hist[c];
                        if (m == 0) continue;
                        const int st = starts[c];
                        const int p4 = (m + 3) & ~3;
                        float a00 = 0.0f, a01 = 0.0f, a10 = 0.0f, a11 = 0.0f;
                        for (int i = 0; i < p4; i += 4) {
                            uint2 dd = *(const uint2*)&pre[st + i + 2 * half];
                            unsigned u0 = buf[(dd.x >> 4) + ((unsigned)lanelow ^ (dd.x & 15u))];
                            unsigned u1 = buf[(dd.y >> 4) + ((unsigned)lanelow ^ (dd.y & 15u))];
                            a00 += __uint_as_float(u0 << 16);
                            a01 += __uint_as_float(u0 & 0xFFFF0000u);
                            a10 += __uint_as_float(u1 << 16);
                            a11 += __uint_as_float(u1 & 0xFFFF0000u);
                        }
                        float aE = a00 + a10, aO = a01 + a11;
                        aE += __shfl_xor_sync(0xffffffffu, aE, 16);
                        aO += __shfl_xor_sync(0xffffffffu, aO, 16);
                        if (half == 0) {     // (c, d-pair) owned by this warp only
                            float2* p2 = (float2*)&sloc[c * DD + ch * DCH + 2 * lanelow];
                            float2 t = *p2;
                            t.x += aE; t.y += aO;
                            *p2 = t;
                        }
                    }
                }
            }
            __syncthreads();   // retire interval
        }
        cur = slot[1];
    }

    // ---- Dump per-block S_local + counts (one atomic pass per block) ----
    __syncthreads();
    for (int i = tid; i < CC * DD; i += THREADS)
        atomicAdd(&g_S[rep][i], sloc[i]);
    if (tid < CC && cntl[tid] > 0) atomicAdd(&g_count[tid], cntl[tid]);

    // sumsq reduction: lane -> warp -> block -> global
    #pragma unroll
    for (int o = 16; o > 0; o >>= 1)
        sumsq += __shfl_xor_sync(0xffffffffu, sumsq, o);
    if (lane == 0) wred[wid] = sumsq;
    __syncthreads();
    if (tid == 0) {
        float s = 0.0f;
        #pragma unroll
        for (int w = 0; w < NWARP; w++) s += wred[w];
        atomicAdd(&g_loss, s);
    }

    // ---- Last-block finalize ----
    __threadfence();
    if (tid == 0) tick[0] = atomicAdd(&g_done, 1u);
    __syncthreads();
    if (tick[0] == GRID - 1) {
        __threadfence();
        float part = 0.0f;
        for (int i = tid; i < CC * DD; i += THREADS) {
            float s = 0.0f;
            #pragma unroll
            for (int r = 0; r < NREP; r++) { s += g_S[r][i]; g_S[r][i] = 0.0f; }
            int   c   = i >> 7;
            int   cnt = g_count[c];
            float cen = centers[i];
            out[1 + i] = (cnt > 0) ? (cen - __fdividef(s, (float)cnt)) : 0.0f;
            part += cen * ((float)cnt * cen - 2.0f * s);   // loss cross terms
        }
        #pragma unroll
        for (int o = 16; o > 0; o >>= 1)
            part += __shfl_xor_sync(0xffffffffu, part, o);
        if (lane == 0) wred[wid] = part;
        __syncthreads();
        if (tid == 0) {
            float t = 0.0f;
            #pragma unroll
            for (int w = 0; w < NWARP; w++) t += wred[w];
            out[0] = (g_loss + t) / 33554432.0f;           // / (N*D)
            g_loss = 0.0f; g_done = 0u; g_ticket = 0u;
        }
        if (tid < CC) g_count[tid] = 0;
    }
}

extern "C" void kernel_launch(void* const* d_in, const int* in_sizes, int n_in,
                              void* d_out, int out_size) {
    const float* feature = 0;
    const int*   label   = 0;
    const float* centers = 0;
    for (int i = 0; i < n_in; i++) {
        if (in_sizes[i] == BB * DD * TT)      feature = (const float*)d_in[i];
        else if (in_sizes[i] == BB * TT)      label   = (const int*)d_in[i];
        else if (in_sizes[i] == CC * DD)      centers = (const float*)d_in[i];
    }
    float* out = (float*)d_out;
    (void)out_size;

    cudaFuncSetAttribute(cl_fused_kernel,
                         cudaFuncAttributeMaxDynamicSharedMemorySize, SM_TOTAL);

    cl_fused_kernel<<<GRID, THREADS, SM_TOTAL>>>(feature, label, centers, out);
}

// round 16
// speedup vs baseline: 1.3297x; 1.3297x over previous
#include <cuda_runtime.h>
#include <cstdint>

// Problem constants
#define BB 128
#define DD 128
#define TT 2048
#define CC 64
#define TILE_T 512
#define NTILE 512
#define DCH 32
#define NCH 4
#define PITCH 33
#define K2_THREADS 1024
#define K2_GRID 152
#define NREP 8

// Scratch (allocation-free; k3/k4 reset for graph replay determinism)
__device__ unsigned short g_order[NTILE * TILE_T];   // row idx grouped by class
__device__ unsigned int   g_hs[NTILE * CC];          // start | (m<<16)
__device__ float          g_S[NREP][CC * DD];
__device__ float          g_loss;
__device__ int            g_count[CC];

// k2 smem: mbarriers + two f32 tile buffers (512 x 33)
#define BUFW   (TILE_T * PITCH)            // 16896 words
#define SM_MB  0                           // full0@0 empty0@8 full1@16 empty1@24
#define SM_B0  64
#define SM_B1  (64 + BUFW * 4)
#define SM_TOT (64 + 2 * BUFW * 4)         // 135232 bytes

// ---------------- k1: per-tile label prep ----------------
__global__ __launch_bounds__(512) void k1_prep(const int* __restrict__ label) {
    __shared__ int hist[CC], starts[CC], cursor[CC], wtot[2];
    const int tid  = threadIdx.x;
    const int lane = tid & 31;
    const int wid  = tid >> 5;
    const int tile = blockIdx.x;
    const int b    = tile >> 2;
    const int t0   = (tile & 3) * TILE_T;

    if (tid < CC) hist[tid] = 0;
    __syncthreads();
    const int myl = label[b * TT + t0 + tid] & (CC - 1);
    atomicAdd(&hist[myl], 1);
    __syncthreads();

    {   // exclusive scan over 64 class sizes
        int m = (tid < CC) ? hist[tid] : 0;
        int incl = m;
        #pragma unroll
        for (int o = 1; o < 32; o <<= 1) {
            int n = __shfl_up_sync(0xffffffffu, incl, o);
            if (lane >= o) incl += n;
        }
        if (wid < 2 && lane == 31) wtot[wid] = incl;
        __syncthreads();
        if (tid < CC) {
            int st = incl - m + (wid == 1 ? wtot[0] : 0);
            starts[tid] = st;
            cursor[tid] = st;
            g_hs[tile * CC + tid] = (unsigned)st | ((unsigned)m << 16);
            atomicAdd(&g_count[tid], m);
        }
        __syncthreads();
    }
    int pos = atomicAdd(&cursor[myl], 1);
    g_order[tile * TILE_T + pos] = (unsigned short)tid;
}

// ---------------- k2: mbarrier pipelined main kernel ----------------
__device__ __forceinline__ uint32_t smem_u32(const void* p) {
    uint32_t a;
    asm("{ .reg .u64 t; cvta.to.shared.u64 t, %1; cvt.u32.u64 %0, t; }"
        : "=r"(a) : "l"(p));
    return a;
}
__device__ __forceinline__ void mb_init(uint32_t a, uint32_t n) {
    asm volatile("mbarrier.init.shared.b64 [%0], %1;" :: "r"(a), "r"(n) : "memory");
}
__device__ __forceinline__ void mb_arrive(uint32_t a) {
    asm volatile("mbarrier.arrive.shared.b64 _, [%0];" :: "r"(a) : "memory");
}
__device__ __forceinline__ void mb_wait(uint32_t a, uint32_t p) {
    asm volatile(
        "{\n\t.reg .pred P;\n\t"
        "WL_%=:\n\t"
        "mbarrier.try_wait.parity.acquire.cta.shared::cta.b64 P, [%0], %1, 0x989680;\n\t"
        "@P bra.uni WD_%=;\n\t"
        "bra.uni WL_%=;\n\t"
        "WD_%=:\n\t}"
        :: "r"(a), "r"(p) : "memory");
}

__global__ __launch_bounds__(K2_THREADS, 1)
void k2_main(const float* __restrict__ feature) {
    extern __shared__ char sm[];
    float* bufs[2] = { (float*)(sm + SM_B0), (float*)(sm + SM_B1) };
    const uint32_t mb = smem_u32(sm) + SM_MB;
    // full0@+0, empty0@+8, full1@+16, empty1@+24

    const int tid  = threadIdx.x;
    const int lane = tid & 31;
    const int wid  = tid >> 5;
    const int cta  = blockIdx.x;
    const int rep  = cta & (NREP - 1);
    const int ntiles = (cta < 56) ? 4 : 3;

    if (tid == 0) {
        mb_init(mb + 0, 16);  mb_init(mb + 8, 16);
        mb_init(mb + 16, 16); mb_init(mb + 24, 16);
    }
    __syncthreads();          // the ONLY block-wide barrier

    if (wid < 16) {
        // ---------------- PRODUCER: 512 threads, R5 load/store geometry ----
        const int t4   = tid & 127;
        const int dd0  = tid >> 7;
        const int sw   = t4 & 31;
        const int trow = t4 * (4 * PITCH);
        const float4* f40 = (const float4*)feature;
        float sumsq = 0.0f;

        for (int ti = 0; ti < ntiles; ti++) {
            const int tile = cta + 152 * ti;
            const int b    = tile >> 2;
            const int t0   = (tile & 3) * TILE_T;
            #pragma unroll
            for (int ch = 0; ch < NCH; ch++) {
                const float4* f4 = f40
                    + ((long long)b * DD + ch * DCH) * (TT / 4) + (t0 >> 2) + t4;
                float4 v[8];
                #pragma unroll
                for (int k = 0; k < 8; k++)
                    v[k] = f4[(long long)(dd0 + 4 * k) * (TT / 4)];
                // wait buffer free (overlaps the LDG latency above)
                mb_wait(mb + 8 + (ch & 1) * 16, (unsigned)(((ch >> 1) & 1) ^ 1));
                float* buf = bufs[ch & 1];
                #pragma unroll
                for (int k = 0; k < 8; k++) {
                    int base = trow + ((dd0 + 4 * k) ^ sw);
                    buf[base]             = v[k].x;
                    buf[base + PITCH]     = v[k].y;
                    buf[base + 2 * PITCH] = v[k].z;
                    buf[base + 3 * PITCH] = v[k].w;
                    sumsq = fmaf(v[k].x, v[k].x, sumsq);
                    sumsq = fmaf(v[k].y, v[k].y, sumsq);
                    sumsq = fmaf(v[k].z, v[k].z, sumsq);
                    sumsq = fmaf(v[k].w, v[k].w, sumsq);
                }
                if (lane == 0) mb_arrive(mb + (ch & 1) * 16);   // full
            }
        }
        #pragma unroll
        for (int o = 16; o > 0; o >>= 1)
            sumsq += __shfl_xor_sync(0xffffffffu, sumsq, o);
        if (lane == 0) atomicAdd(&g_loss, sumsq);
    } else {
        // ---------------- CONSUMER: 16 warps, 4 fixed classes each --------
        const int cw = wid - 16;
        float acc[4][4];
        #pragma unroll
        for (int i = 0; i < 4; i++)
            #pragma unroll
            for (int c4 = 0; c4 < 4; c4++) acc[i][c4] = 0.0f;

        for (int ti = 0; ti < ntiles; ti++) {
            const int tile = cta + 152 * ti;
            int m[4], st[4];
            #pragma unroll
            for (int i = 0; i < 4; i++) {
                unsigned h = g_hs[tile * CC + cw + 16 * i];
                st[i] = (int)(h & 0xffffu);
                m[i]  = (int)(h >> 16);
            }
            const unsigned short* ord = &g_order[tile * TILE_T];
            #pragma unroll
            for (int ch = 0; ch < NCH; ch++) {
                mb_wait(mb + (ch & 1) * 16, (unsigned)((ch >> 1) & 1));  // full
                const float* buf = bufs[ch & 1];
                #pragma unroll
                for (int i = 0; i < 4; i++) {
                    const int mm = m[i];
                    if (mm == 0) continue;
                    const unsigned short* o = ord + st[i];
                    float s0 = 0.0f, s1 = 0.0f;
                    int j = 0;
                    for (; j + 1 < mm; j += 2) {
                        int ta = o[j];
                        int tb = o[j + 1];
                        s0 += buf[ta * PITCH + (lane ^ ((ta >> 2) & 31))];
                        s1 += buf[tb * PITCH + (lane ^ ((tb >> 2) & 31))];
                    }
                    if (j < mm) {
                        int ta = o[j];
                        s0 += buf[ta * PITCH + (lane ^ ((ta >> 2) & 31))];
                    }
                    acc[i][ch] += s0 + s1;
                }
                if (lane == 0) mb_arrive(mb + 8 + (ch & 1) * 16);        // empty
            }
        }
        // flush register accumulators (only atomics in the kernel)
        #pragma unroll
        for (int i = 0; i < 4; i++)
            #pragma unroll
            for (int ch = 0; ch < NCH; ch++)
                atomicAdd(&g_S[rep][(cw + 16 * i) * DD + ch * DCH + lane],
                          acc[i][ch]);
    }
}

// ---------------- k3: difference + cross terms; reset S/count ----------------
__global__ __launch_bounds__(512) void k3_fin(const float* __restrict__ centers,
                                              float* __restrict__ out) {
    const int tid = threadIdx.x;
    const int i   = blockIdx.x * 512 + tid;
    float part = 0.0f;
    {
        float s = 0.0f;
        #pragma unroll
        for (int r = 0; r < NREP; r++) { s += g_S[r][i]; g_S[r][i] = 0.0f; }
        int   c   = i >> 7;
        int   cnt = g_count[c];
        float cen = centers[i];
        out[1 + i] = (cnt > 0) ? (cen - __fdividef(s, (float)cnt)) : 0.0f;
        part = cen * ((float)cnt * cen - 2.0f * s);       // loss cross terms
    }
    __shared__ float wred[16];
    const int lane = tid & 31, wid = tid >> 5;
    #pragma unroll
    for (int o = 16; o > 0; o >>= 1)
        part += __shfl_xor_sync(0xffffffffu, part, o);
    if (lane == 0) wred[wid] = part;
    __syncthreads();
    if (tid == 0) {
        float s = 0.0f;
        #pragma unroll
        for (int w = 0; w < 16; w++) s += wred[w];
        atomicAdd(&g_loss, s);
    }
    // reset counts for this block's classes (exclusively owned: i-range = 4 classes)
    __syncthreads();
    if (tid < 4) g_count[blockIdx.x * 4 + tid] = 0;
}

// ---------------- k4: loss writeback + reset ----------------
__global__ void k4_loss(float* __restrict__ out) {
    out[0] = g_loss / 33554432.0f;      // / (N*D)
    g_loss = 0.0f;
}

extern "C" void kernel_launch(void* const* d_in, const int* in_sizes, int n_in,
                              void* d_out, int out_size) {
    const float* feature = 0;
    const int*   label   = 0;
    const float* centers = 0;
    for (int i = 0; i < n_in; i++) {
        if (in_sizes[i] == BB * DD * TT)      feature = (const float*)d_in[i];
        else if (in_sizes[i] == BB * TT)      label   = (const int*)d_in[i];
        else if (in_sizes[i] == CC * DD)      centers = (const float*)d_in[i];
    }
    float* out = (float*)d_out;
    (void)out_size;

    cudaFuncSetAttribute(k2_main,
                         cudaFuncAttributeMaxDynamicSharedMemorySize, SM_TOT);

    k1_prep<<<NTILE, 512>>>(label);
    k2_main<<<K2_GRID, K2_THREADS, SM_TOT>>>(feature);
    k3_fin<<<CC * DD / 512, 512>>>(centers, out);
    k4_loss<<<1, 1>>>(out);
}